// round 1
// baseline (speedup 1.0000x reference)
#include <cuda_runtime.h>

// CrossSpatialWindowAttention — fused fp32 baseline.
// One block per 8x8 window. Stages: load x_kv window + Wk -> K proj -> Wv -> V proj
// -> load x_q + Wq -> Q proj -> (preload Wo) -> per-head scores/softmax/AV -> Wo proj -> store.

namespace {

constexpr int IMG     = 256;
constexpr int CQ      = 96;
constexpr int CKV     = 192;
constexpr int S       = 96;    // shared / qkv dim
constexpr int NH      = 6;
constexpr int WIN     = 64;
constexpr int THREADS = 256;

// shared memory layout (floats)
constexpr int OFF_X = 0;               // [192][64]  input window (x_kv, then x_q in rows 0..95)
constexpr int OFF_W = 12288;           // [192*96]   staged weight matrix
constexpr int OFF_Q = 30720;           // [96][64]
constexpr int OFF_K = 36864;           // [96][64]
constexpr int OFF_V = 43008;           // [96][64]
constexpr int SMEM_FLOATS = 49152;     // 192 KB
// reuse of the X region once inputs are consumed:
constexpr int OFF_O = 0;               // [96][64]   attention output (channel-major)
constexpr int OFF_A = 6144;            // [64][65]   attn scores/probs for one head

// GEMM: sOut[c][t] = sum_k sIn[k][t] * sW[k][c] + bias[c]
// thread microtile: 4 tokens x 6 channels (16 t-groups x 16 c-groups = 256 threads)
template <int K>
__device__ __forceinline__ void proj_gemm(const float* __restrict__ sIn,
                                          const float* __restrict__ sWm,
                                          const float* __restrict__ bias,
                                          float* __restrict__ sOut, int tid) {
    const int t0 = (tid & 15) * 4;
    const int c0 = (tid >> 4) * 6;
    float acc[6][4];
#pragma unroll
    for (int a = 0; a < 6; a++)
#pragma unroll
        for (int u = 0; u < 4; u++) acc[a][u] = 0.f;

#pragma unroll 4
    for (int k = 0; k < K; k++) {
        const float4 xv = *reinterpret_cast<const float4*>(&sIn[k * 64 + t0]);
        const float2* wp = reinterpret_cast<const float2*>(&sWm[k * 96 + c0]);
        const float2 w01 = wp[0], w23 = wp[1], w45 = wp[2];
        const float wv[6] = {w01.x, w01.y, w23.x, w23.y, w45.x, w45.y};
#pragma unroll
        for (int a = 0; a < 6; a++) {
            acc[a][0] = fmaf(wv[a], xv.x, acc[a][0]);
            acc[a][1] = fmaf(wv[a], xv.y, acc[a][1]);
            acc[a][2] = fmaf(wv[a], xv.z, acc[a][2]);
            acc[a][3] = fmaf(wv[a], xv.w, acc[a][3]);
        }
    }
#pragma unroll
    for (int a = 0; a < 6; a++) {
        const float bb = bias[c0 + a];
        float4 r = make_float4(acc[a][0] + bb, acc[a][1] + bb,
                               acc[a][2] + bb, acc[a][3] + bb);
        *reinterpret_cast<float4*>(&sOut[(c0 + a) * 64 + t0]) = r;
    }
}

__global__ void __launch_bounds__(THREADS, 1)
xswa_kernel(const float* __restrict__ xq, const float* __restrict__ xkv,
            const float* __restrict__ Wq, const float* __restrict__ bq,
            const float* __restrict__ Wk, const float* __restrict__ bk,
            const float* __restrict__ Wv, const float* __restrict__ bv,
            const float* __restrict__ bias_table,
            const float* __restrict__ Wo, const float* __restrict__ bo,
            float* __restrict__ out) {
    extern __shared__ float sm[];
    float* sX = sm + OFF_X;
    float* sW = sm + OFF_W;
    float* sQ = sm + OFF_Q;
    float* sK = sm + OFF_K;
    float* sV = sm + OFF_V;
    float* sO = sm + OFF_O;
    float* sA = sm + OFF_A;

    const int tid = threadIdx.x;
    const int win = blockIdx.x;
    const int b   = win >> 10;          // 1024 windows per batch image
    const int rem = win & 1023;
    const int h0  = (rem >> 5) << 3;
    const int w0  = (rem & 31) << 3;

    const float* xq_b  = xq  + (size_t)b * CQ  * (IMG * IMG);
    const float* xkv_b = xkv + (size_t)b * CKV * (IMG * IMG);

    // ---- load x_kv window (channel-major [192][64]) + Wk ----
#pragma unroll 4
    for (int idx = tid; idx < CKV * WIN; idx += THREADS) {
        const int c = idx >> 6, t = idx & 63;
        sX[idx] = xkv_b[(size_t)(c * IMG + h0 + (t >> 3)) * IMG + w0 + (t & 7)];
    }
#pragma unroll
    for (int idx = tid; idx < CKV * S / 4; idx += THREADS)
        reinterpret_cast<float4*>(sW)[idx] = reinterpret_cast<const float4*>(Wk)[idx];
    __syncthreads();

    proj_gemm<CKV>(sX, sW, bk, sK, tid);    // K = x_kv @ Wk + bk
    __syncthreads();

#pragma unroll
    for (int idx = tid; idx < CKV * S / 4; idx += THREADS)
        reinterpret_cast<float4*>(sW)[idx] = reinterpret_cast<const float4*>(Wv)[idx];
    __syncthreads();

    proj_gemm<CKV>(sX, sW, bv, sV, tid);    // V = x_kv @ Wv + bv
    __syncthreads();

    // ---- load x_q window (rows 0..95 of sX) + Wq ----
#pragma unroll 4
    for (int idx = tid; idx < CQ * WIN; idx += THREADS) {
        const int c = idx >> 6, t = idx & 63;
        sX[idx] = xq_b[(size_t)(c * IMG + h0 + (t >> 3)) * IMG + w0 + (t & 7)];
    }
#pragma unroll
    for (int idx = tid; idx < CQ * S / 4; idx += THREADS)
        reinterpret_cast<float4*>(sW)[idx] = reinterpret_cast<const float4*>(Wq)[idx];
    __syncthreads();

    proj_gemm<CQ>(sX, sW, bq, sQ, tid);     // Q = x_q @ Wq + bq
    __syncthreads();

    // Preload Wo into sW; consumed only after the head loop's final barrier.
#pragma unroll
    for (int idx = tid; idx < S * CQ / 4; idx += THREADS)
        reinterpret_cast<float4*>(sW)[idx] = reinterpret_cast<const float4*>(Wo)[idx];

    // ---- attention, one head at a time ----
    for (int h = 0; h < NH; h++) {
        // scores: attn[i][j] = 0.25 * sum_d q[i][d] k[j][d] + rel_bias(h,i,j)
        {
            const int i0 = (tid & 15) * 4;
            const int j0 = (tid >> 4) * 4;
            const float* q = sQ + h * 16 * 64;
            const float* k = sK + h * 16 * 64;
            float acc[4][4];
#pragma unroll
            for (int u = 0; u < 4; u++)
#pragma unroll
                for (int v = 0; v < 4; v++) acc[u][v] = 0.f;
#pragma unroll
            for (int d = 0; d < 16; d++) {
                const float4 qv = *reinterpret_cast<const float4*>(&q[d * 64 + i0]);
                const float4 kv = *reinterpret_cast<const float4*>(&k[d * 64 + j0]);
                const float qa[4] = {qv.x, qv.y, qv.z, qv.w};
                const float ka[4] = {kv.x, kv.y, kv.z, kv.w};
#pragma unroll
                for (int u = 0; u < 4; u++)
#pragma unroll
                    for (int v = 0; v < 4; v++)
                        acc[u][v] = fmaf(qa[u], ka[v], acc[u][v]);
            }
#pragma unroll
            for (int u = 0; u < 4; u++) {
                const int i = i0 + u;
                const int ih = i >> 3, iw = i & 7;
#pragma unroll
                for (int v = 0; v < 4; v++) {
                    const int j = j0 + v;
                    const int rel = (ih - (j >> 3) + 7) * 15 + (iw - (j & 7) + 7);
                    sA[i * 65 + j] = acc[u][v] * 0.25f + bias_table[rel * NH + h];
                }
            }
        }
        __syncthreads();

        // softmax over j, one warp per row (8 warps x 8 rows)
        {
            const int warp = tid >> 5, lane = tid & 31;
            for (int r = warp; r < WIN; r += 8) {
                float v0 = sA[r * 65 + lane];
                float v1 = sA[r * 65 + 32 + lane];
                float m = fmaxf(v0, v1);
#pragma unroll
                for (int o = 16; o > 0; o >>= 1)
                    m = fmaxf(m, __shfl_xor_sync(0xffffffffu, m, o));
                const float e0 = __expf(v0 - m);
                const float e1 = __expf(v1 - m);
                float s = e0 + e1;
#pragma unroll
                for (int o = 16; o > 0; o >>= 1)
                    s += __shfl_xor_sync(0xffffffffu, s, o);
                const float inv = 1.f / s;
                sA[r * 65 + lane]      = e0 * inv;
                sA[r * 65 + 32 + lane] = e1 * inv;
            }
        }
        __syncthreads();

        // AV: out[i][d] = sum_j p[i][j] v[j][d]; thread tile: i in {ci, ci+32}, d in {2cd, 2cd+1}
        {
            const int ci = tid & 31;
            const int cd = tid >> 5;
            const float* v = sV + (h * 16 + 2 * cd) * 64;
            float a00 = 0.f, a01 = 0.f, a10 = 0.f, a11 = 0.f;
#pragma unroll 8
            for (int j = 0; j < WIN; j++) {
                const float p0 = sA[ci * 65 + j];
                const float p1 = sA[(ci + 32) * 65 + j];
                const float v0 = v[j];
                const float v1 = v[64 + j];
                a00 = fmaf(p0, v0, a00);
                a01 = fmaf(p0, v1, a01);
                a10 = fmaf(p1, v0, a10);
                a11 = fmaf(p1, v1, a11);
            }
            float* o = sO + (h * 16 + 2 * cd) * 64;
            o[ci]           = a00;
            o[64 + ci]      = a01;
            o[ci + 32]      = a10;
            o[64 + ci + 32] = a11;
        }
        __syncthreads();
    }

    // ---- output projection + store: out[b][c][h0+i][w0+j] ----
    {
        const int t0 = (tid & 15) * 4;
        const int c0 = (tid >> 4) * 6;
        float acc[6][4];
#pragma unroll
        for (int a = 0; a < 6; a++)
#pragma unroll
            for (int u = 0; u < 4; u++) acc[a][u] = 0.f;

#pragma unroll 4
        for (int k = 0; k < S; k++) {
            const float4 xv = *reinterpret_cast<const float4*>(&sO[k * 64 + t0]);
            const float2* wp = reinterpret_cast<const float2*>(&sW[k * 96 + c0]);
            const float2 w01 = wp[0], w23 = wp[1], w45 = wp[2];
            const float wv[6] = {w01.x, w01.y, w23.x, w23.y, w45.x, w45.y};
#pragma unroll
            for (int a = 0; a < 6; a++) {
                acc[a][0] = fmaf(wv[a], xv.x, acc[a][0]);
                acc[a][1] = fmaf(wv[a], xv.y, acc[a][1]);
                acc[a][2] = fmaf(wv[a], xv.z, acc[a][2]);
                acc[a][3] = fmaf(wv[a], xv.w, acc[a][3]);
            }
        }
        const int i = t0 >> 3, j = t0 & 7;   // 4 consecutive tokens stay in one image row
        const size_t base = (size_t)b * CQ * (IMG * IMG)
                          + (size_t)(h0 + i) * IMG + (w0 + j);
#pragma unroll
        for (int a = 0; a < 6; a++) {
            const float bb = bo[c0 + a];
            float4 r = make_float4(acc[a][0] + bb, acc[a][1] + bb,
                                   acc[a][2] + bb, acc[a][3] + bb);
            *reinterpret_cast<float4*>(&out[base + (size_t)(c0 + a) * (IMG * IMG)]) = r;
        }
    }
}

} // namespace

extern "C" void kernel_launch(void* const* d_in, const int* in_sizes, int n_in,
                              void* d_out, int out_size) {
    const float* xq   = (const float*)d_in[0];
    const float* xkv  = (const float*)d_in[1];
    const float* Wq   = (const float*)d_in[2];
    const float* bq   = (const float*)d_in[3];
    const float* Wk   = (const float*)d_in[4];
    const float* bk   = (const float*)d_in[5];
    const float* Wv   = (const float*)d_in[6];
    const float* bv   = (const float*)d_in[7];
    const float* bias_table = (const float*)d_in[8];
    const float* Wo   = (const float*)d_in[9];
    const float* bo   = (const float*)d_in[10];
    float* out = (float*)d_out;

    const int B = in_sizes[0] / (CQ * IMG * IMG);
    const int nwin = B * (IMG / 8) * (IMG / 8);

    const int smem_bytes = SMEM_FLOATS * (int)sizeof(float);
    cudaFuncSetAttribute(xswa_kernel, cudaFuncAttributeMaxDynamicSharedMemorySize, smem_bytes);

    xswa_kernel<<<nwin, THREADS, smem_bytes>>>(xq, xkv, Wq, bq, Wk, bk, Wv, bv,
                                               bias_table, Wo, bo, out);
}

// round 2
// speedup vs baseline: 1.0853x; 1.0853x over previous
#include <cuda_runtime.h>

// CrossSpatialWindowAttention — fused fp32, 512 threads, 2-heads-per-phase.
// One block per 8x8 window, 192KB smem, 1 CTA/SM, 16 warps.

namespace {

constexpr int IMG     = 256;
constexpr int CQ      = 96;
constexpr int CKV     = 192;
constexpr int S       = 96;
constexpr int NH      = 6;
constexpr int WIN     = 64;
constexpr int THREADS = 512;

// shared memory layout (floats)
constexpr int OFF_X   = 0;          // [192][64] inputs (x_kv, then x_q rows 0..95)
constexpr int OFF_W   = 12288;      // staged weights (up to 192x96)
constexpr int OFF_Q   = 30720;      // [96][64]
constexpr int OFF_K   = 36864;      // [96][64]
constexpr int OFF_V   = 43008;      // [96][64]
constexpr int SMEM_FLOATS = 49152;  // 192 KB
// reuse once inputs consumed:
constexpr int OFF_A    = 0;                 // [128][65] probs for 2 heads (8320)
constexpr int OFF_BIAS = 8448;              // [225][6] staged bias table (1350)
constexpr int OFF_O    = OFF_W + 9216;      // [96][64] attn out (21504..27648), after Wo

// GEMM: sOut[c][t] = sum_k sIn[k][t] * sW[k][c] + bias[c]
// 512 threads: lane pair of tokens (t0 = (tid&31)*2), warp owns 6 channels.
// Weight loads are warp-broadcast; token loads conflict-free.
template <int K>
__device__ __forceinline__ void proj_gemm(const float* __restrict__ sIn,
                                          const float* __restrict__ sWm,
                                          const float* __restrict__ bias,
                                          float* __restrict__ sOut, int tid) {
    const int t0 = (tid & 31) * 2;
    const int c0 = (tid >> 5) * 6;
    float acc[6][2];
#pragma unroll
    for (int a = 0; a < 6; a++) { acc[a][0] = 0.f; acc[a][1] = 0.f; }

#pragma unroll 4
    for (int k = 0; k < K; k++) {
        const float2 xv = *reinterpret_cast<const float2*>(&sIn[k * 64 + t0]);
        const float2* wp = reinterpret_cast<const float2*>(&sWm[k * 96 + c0]);
        const float2 w01 = wp[0], w23 = wp[1], w45 = wp[2];
        const float wv[6] = {w01.x, w01.y, w23.x, w23.y, w45.x, w45.y};
#pragma unroll
        for (int a = 0; a < 6; a++) {
            acc[a][0] = fmaf(wv[a], xv.x, acc[a][0]);
            acc[a][1] = fmaf(wv[a], xv.y, acc[a][1]);
        }
    }
#pragma unroll
    for (int a = 0; a < 6; a++) {
        const float bb = bias[c0 + a];
        float2 r = make_float2(acc[a][0] + bb, acc[a][1] + bb);
        *reinterpret_cast<float2*>(&sOut[(c0 + a) * 64 + t0]) = r;
    }
}

__global__ void __launch_bounds__(THREADS, 1)
xswa_kernel(const float* __restrict__ xq, const float* __restrict__ xkv,
            const float* __restrict__ Wq, const float* __restrict__ bq,
            const float* __restrict__ Wk, const float* __restrict__ bk,
            const float* __restrict__ Wv, const float* __restrict__ bv,
            const float* __restrict__ bias_table,
            const float* __restrict__ Wo, const float* __restrict__ bo,
            float* __restrict__ out) {
    extern __shared__ float sm[];
    float* sX = sm + OFF_X;
    float* sW = sm + OFF_W;
    float* sQ = sm + OFF_Q;
    float* sK = sm + OFF_K;
    float* sV = sm + OFF_V;
    float* sA = sm + OFF_A;
    float* sB = sm + OFF_BIAS;
    float* sO = sm + OFF_O;

    const int tid = threadIdx.x;
    const int win = blockIdx.x;
    const int b   = win >> 10;
    const int rem = win & 1023;
    const int h0  = (rem >> 5) << 3;
    const int w0  = (rem & 31) << 3;

    const float* xq_b  = xq  + (size_t)b * CQ  * (IMG * IMG);
    const float* xkv_b = xkv + (size_t)b * CKV * (IMG * IMG);

    // ---- load x_kv window (channel-major [192][64]) + Wk ----
#pragma unroll 4
    for (int idx = tid; idx < CKV * WIN; idx += THREADS) {
        const int c = idx >> 6, t = idx & 63;
        sX[idx] = xkv_b[(size_t)(c * IMG + h0 + (t >> 3)) * IMG + w0 + (t & 7)];
    }
#pragma unroll
    for (int idx = tid; idx < CKV * S / 4; idx += THREADS)
        reinterpret_cast<float4*>(sW)[idx] = reinterpret_cast<const float4*>(Wk)[idx];
    __syncthreads();

    proj_gemm<CKV>(sX, sW, bk, sK, tid);
    __syncthreads();

#pragma unroll
    for (int idx = tid; idx < CKV * S / 4; idx += THREADS)
        reinterpret_cast<float4*>(sW)[idx] = reinterpret_cast<const float4*>(Wv)[idx];
    __syncthreads();

    proj_gemm<CKV>(sX, sW, bv, sV, tid);
    __syncthreads();

    // ---- x_q + Wq ----
#pragma unroll 2
    for (int idx = tid; idx < CQ * WIN; idx += THREADS) {
        const int c = idx >> 6, t = idx & 63;
        sX[idx] = xq_b[(size_t)(c * IMG + h0 + (t >> 3)) * IMG + w0 + (t & 7)];
    }
#pragma unroll
    for (int idx = tid; idx < CQ * S / 4; idx += THREADS)
        reinterpret_cast<float4*>(sW)[idx] = reinterpret_cast<const float4*>(Wq)[idx];
    __syncthreads();

    proj_gemm<CQ>(sX, sW, bq, sQ, tid);
    __syncthreads();

    // ---- stage Wo + bias table (x_q region dead now) ----
#pragma unroll
    for (int idx = tid; idx < S * CQ / 4; idx += THREADS)
        reinterpret_cast<float4*>(sW)[idx] = reinterpret_cast<const float4*>(Wo)[idx];
    for (int idx = tid; idx < 225 * NH; idx += THREADS)
        sB[idx] = bias_table[idx];
    __syncthreads();

    // ---- attention, two heads at a time ----
    for (int h = 0; h < NH; h += 2) {
        const int sub = tid >> 8;          // which of the 2 heads
        const int t   = tid & 255;
        const int hh  = h + sub;

        // scores: A[sub*64+i][j] = 0.25*sum_d q[i][d]k[j][d] + bias
        {
            const int i0 = (t & 15) * 4;
            const int j0 = (t >> 4) * 4;
            const float* q = sQ + hh * 16 * 64;
            const float* k = sK + hh * 16 * 64;
            float acc[4][4];
#pragma unroll
            for (int u = 0; u < 4; u++)
#pragma unroll
                for (int v = 0; v < 4; v++) acc[u][v] = 0.f;
#pragma unroll
            for (int d = 0; d < 16; d++) {
                const float4 qv = *reinterpret_cast<const float4*>(&q[d * 64 + i0]);
                const float4 kv = *reinterpret_cast<const float4*>(&k[d * 64 + j0]);
                const float qa[4] = {qv.x, qv.y, qv.z, qv.w};
                const float ka[4] = {kv.x, kv.y, kv.z, kv.w};
#pragma unroll
                for (int u = 0; u < 4; u++)
#pragma unroll
                    for (int v = 0; v < 4; v++)
                        acc[u][v] = fmaf(qa[u], ka[v], acc[u][v]);
            }
#pragma unroll
            for (int u = 0; u < 4; u++) {
                const int i = i0 + u;
                const int ih = i >> 3, iw = i & 7;
#pragma unroll
                for (int v = 0; v < 4; v++) {
                    const int j = j0 + v;
                    const int rel = (ih - (j >> 3) + 7) * 15 + (iw - (j & 7) + 7);
                    sA[(sub * 64 + i) * 65 + j] = acc[u][v] * 0.25f + sB[rel * NH + hh];
                }
            }
        }
        __syncthreads();

        // softmax: 128 rows over 16 warps
        {
            const int warp = tid >> 5, lane = tid & 31;
#pragma unroll
            for (int r = warp; r < 2 * WIN; r += 16) {
                float v0 = sA[r * 65 + lane];
                float v1 = sA[r * 65 + 32 + lane];
                float m = fmaxf(v0, v1);
#pragma unroll
                for (int o = 16; o > 0; o >>= 1)
                    m = fmaxf(m, __shfl_xor_sync(0xffffffffu, m, o));
                const float e0 = __expf(v0 - m);
                const float e1 = __expf(v1 - m);
                float s = e0 + e1;
#pragma unroll
                for (int o = 16; o > 0; o >>= 1)
                    s += __shfl_xor_sync(0xffffffffu, s, o);
                const float inv = 1.f / s;
                sA[r * 65 + lane]      = e0 * inv;
                sA[r * 65 + 32 + lane] = e1 * inv;
            }
        }
        __syncthreads();

        // AV: out[i][d] = sum_j p[i][j] v[j][d]; per head: 256 threads,
        // thread tile i in {ci, ci+32}, d in {2cd, 2cd+1}
        {
            const int ci = t & 31;
            const int cd = t >> 5;
            const float* p = sA + (sub * 64) * 65;
            const float* v = sV + (hh * 16 + 2 * cd) * 64;
            float a00 = 0.f, a01 = 0.f, a10 = 0.f, a11 = 0.f;
#pragma unroll 8
            for (int j = 0; j < WIN; j++) {
                const float p0 = p[ci * 65 + j];
                const float p1 = p[(ci + 32) * 65 + j];
                const float v0 = v[j];
                const float v1 = v[64 + j];
                a00 = fmaf(p0, v0, a00);
                a01 = fmaf(p0, v1, a01);
                a10 = fmaf(p1, v0, a10);
                a11 = fmaf(p1, v1, a11);
            }
            float* o = sO + (hh * 16 + 2 * cd) * 64;
            o[ci]           = a00;
            o[64 + ci]      = a01;
            o[ci + 32]      = a10;
            o[64 + ci + 32] = a11;
        }
        __syncthreads();
    }

    // ---- output projection + store ----
    {
        const int t0 = (tid & 31) * 2;
        const int c0 = (tid >> 5) * 6;
        float acc[6][2];
#pragma unroll
        for (int a = 0; a < 6; a++) { acc[a][0] = 0.f; acc[a][1] = 0.f; }

#pragma unroll 4
        for (int k = 0; k < S; k++) {
            const float2 xv = *reinterpret_cast<const float2*>(&sO[k * 64 + t0]);
            const float2* wp = reinterpret_cast<const float2*>(&sW[k * 96 + c0]);
            const float2 w01 = wp[0], w23 = wp[1], w45 = wp[2];
            const float wv[6] = {w01.x, w01.y, w23.x, w23.y, w45.x, w45.y};
#pragma unroll
            for (int a = 0; a < 6; a++) {
                acc[a][0] = fmaf(wv[a], xv.x, acc[a][0]);
                acc[a][1] = fmaf(wv[a], xv.y, acc[a][1]);
            }
        }
        const int i = t0 >> 3, j = t0 & 7;   // 2 consecutive tokens, same image row
        const size_t base = (size_t)b * CQ * (IMG * IMG)
                          + (size_t)(h0 + i) * IMG + (w0 + j);
#pragma unroll
        for (int a = 0; a < 6; a++) {
            const float bb = bo[c0 + a];
            float2 r = make_float2(acc[a][0] + bb, acc[a][1] + bb);
            *reinterpret_cast<float2*>(&out[base + (size_t)(c0 + a) * (IMG * IMG)]) = r;
        }
    }
}

} // namespace

extern "C" void kernel_launch(void* const* d_in, const int* in_sizes, int n_in,
                              void* d_out, int out_size) {
    const float* xq   = (const float*)d_in[0];
    const float* xkv  = (const float*)d_in[1];
    const float* Wq   = (const float*)d_in[2];
    const float* bq   = (const float*)d_in[3];
    const float* Wk   = (const float*)d_in[4];
    const float* bk   = (const float*)d_in[5];
    const float* Wv   = (const float*)d_in[6];
    const float* bv   = (const float*)d_in[7];
    const float* bias_table = (const float*)d_in[8];
    const float* Wo   = (const float*)d_in[9];
    const float* bo   = (const float*)d_in[10];
    float* out = (float*)d_out;

    const int B = in_sizes[0] / (CQ * IMG * IMG);
    const int nwin = B * (IMG / 8) * (IMG / 8);

    const int smem_bytes = SMEM_FLOATS * (int)sizeof(float);
    cudaFuncSetAttribute(xswa_kernel, cudaFuncAttributeMaxDynamicSharedMemorySize, smem_bytes);

    xswa_kernel<<<nwin, THREADS, smem_bytes>>>(xq, xkv, Wq, bq, Wk, bk, Wv, bv,
                                               bias_table, Wo, bo, out);
}